// round 5
// baseline (speedup 1.0000x reference)
#include <cuda_runtime.h>
#include <math.h>

typedef unsigned long long u64;

#define NB 4
#define NA 256
#define GSZ 12
#define NGR 1728
#define KA 8
#define KG 32
#define NL 4
#define CODE 64
#define HID 128
#define EDGEF 64
#define NGAUSS 20
#define NATOM (NB*NA)          // 1024
#define NGRID (NB*NGR)         // 6912
#define NNODE (NATOM+NGRID)    // 7936
#define MIROWS (2*CODE+EDGEF)  // 192

#define PD_BLOCKS 256
#define PS_BLOCKS 40
#define EDGE_BLOCKS 888
#define POST_BLOCKS 740
#define CLIPBIT (1 << 30)
#define NMASK 0xFFFF
#define NEDGE (NATOM*KA + NGRID*KG)   // 229376

// ---------------- static device scratch ----------------
__device__ float g_h[2][NNODE*CODE];
__device__ float g_npos[NNODE*3];
__device__ int   g_nbrA[NATOM][KA];
__device__ int   g_nbrG[NGRID][KG];
__device__ float4 g_gsA[NATOM*KA*5];
__device__ float4 g_gsG[NGRID*KG*5];
__device__ float g_Psrc[NATOM*HID];
__device__ float g_Pdst[NNODE*HID];
__device__ float g_HS[NNODE*HID];       // per-node hidden sums (stage-1 output)
__device__ float g_EW1[NL][NGAUSS*HID];
__device__ float g_b1eff[NL][HID];
__device__ float g_C[NL][HID];

struct GaussC { float off[NGAUSS]; float coeff2[NGAUSS]; float g5[NGAUSS]; };

// ---------------- f32x2 helpers ----------------
__device__ __forceinline__ void ffma2(u64 &d, u64 a, u64 b) {
    asm("fma.rn.f32x2 %0, %1, %2, %0;" : "+l"(d) : "l"(a), "l"(b));
}
__device__ __forceinline__ u64 add2(u64 a, u64 b) {
    u64 r; asm("add.rn.f32x2 %0, %1, %2;" : "=l"(r) : "l"(a), "l"(b)); return r;
}
__device__ __forceinline__ u64 pk(float x, float y) {
    u64 r; asm("mov.b64 %0, {%1, %2};" : "=l"(r) : "f"(x), "f"(y)); return r;
}
__device__ __forceinline__ float2 upk(u64 v) {
    float2 r; asm("mov.b64 {%0, %1}, %2;" : "=f"(r.x), "=f"(r.y) : "l"(v)); return r;
}
__device__ __forceinline__ void barhalf(int id) {
    asm volatile("bar.sync %0, %1;" :: "r"(id), "r"(64) : "memory");
}

// ================= k_setup: init + knn_a + knn_g + prep, one launch =================
__global__ void __launch_bounds__(128) k_setup(
    const float* __restrict__ pos, const int* __restrict__ atype,
    const float* __restrict__ edge_W, const float* __restrict__ edge_b,
    const float* __restrict__ W1, const float* __restrict__ b1, GaussC gc)
{
    __shared__ float sx[NA], sy[NA], sz[NA];
    int bid = blockIdx.x, t = threadIdx.x;

    if (bid < 248) {
        for (int i = bid * 128 + t; i < NNODE * CODE; i += 248 * 128) {
            int n = i >> 6, c = i & 63;
            g_h[0][i] = (n < NATOM && c == atype[n]) ? 1.f : 0.f;
        }
        for (int i = bid * 128 + t; i < NNODE; i += 248 * 128) {
            float x, y, z;
            if (i < NATOM) { x = pos[i*3]; y = pos[i*3+1]; z = pos[i*3+2]; }
            else {
                int g = (i - NATOM) % NGR;
                int ix = g / (GSZ*GSZ), iy = (g / GSZ) % GSZ, iz = g % GSZ;
                x = -8.25f + 1.5f*ix; y = -8.25f + 1.5f*iy; z = -8.25f + 1.5f*iz;
            }
            g_npos[i*3] = x; g_npos[i*3+1] = y; g_npos[i*3+2] = z;
        }
    } else if (bid < 248 + 256) {
        // ---- atom kNN (warp per node, stable ties) ----
        int abid = bid - 248;
        int lane = t & 31, w = t >> 5;
        int b = (abid * 4) / NA;
        for (int j = t; j < NA; j += 128) {
            int gj = b * NA + j;
            sx[j] = pos[gj*3]; sy[j] = pos[gj*3+1]; sz[j] = pos[gj*3+2];
        }
        __syncthreads();
        int il = (abid * 4 + w) % NA;
        float px = sx[il], py = sy[il], pz = sz[il];
        float d[8];
#pragma unroll
        for (int q = 0; q < 8; q++) {
            int j = q * 32 + lane;
            float dx = sx[j]-px, dy = sy[j]-py, dz = sz[j]-pz;
            float dd = dx*dx + dy*dy + dz*dz;
            d[q] = (j == il) ? 1e30f : dd;
        }
        int keep = 0;
        for (int r = 0; r < KA; r++) {
            float mv = d[0]; int mq = 0;
#pragma unroll
            for (int q = 1; q < 8; q++) if (d[q] < mv) { mv = d[q]; mq = q; }
            int mj = mq * 32 + lane;
#pragma unroll
            for (int off = 16; off; off >>= 1) {
                float ov = __shfl_xor_sync(0xffffffffu, mv, off);
                int   oj = __shfl_xor_sync(0xffffffffu, mj, off);
                if (ov < mv || (ov == mv && oj < mj)) { mv = ov; mj = oj; }
            }
            if (lane == r) keep = mj;
            if ((mj & 31) == lane) {
                int q = mj >> 5;
#pragma unroll
                for (int qq = 0; qq < 8; qq++) if (qq == q) d[qq] = 1e30f;
            }
        }
        if (lane < KA) g_nbrA[b * NA + il][lane] = b * NA + keep;
    } else if (bid < 248 + 256 + 1728) {
        // ---- grid kNN ----
        int gbid = bid - 504;
        int lane = t & 31, w = t >> 5;
        int b = (gbid * 4) / NGR;
        for (int j = t; j < NA; j += 128) {
            int gj = b * NA + j;
            sx[j] = pos[gj*3]; sy[j] = pos[gj*3+1]; sz[j] = pos[gj*3+2];
        }
        __syncthreads();
        int gl = (gbid * 4 + w) % NGR;
        int ix = gl / (GSZ*GSZ), iy = (gl / GSZ) % GSZ, iz = gl % GSZ;
        float px = -8.25f + 1.5f*ix, py = -8.25f + 1.5f*iy, pz = -8.25f + 1.5f*iz;
        float d[8];
#pragma unroll
        for (int q = 0; q < 8; q++) {
            int j = q * 32 + lane;
            float dx = sx[j]-px, dy = sy[j]-py, dz = sz[j]-pz;
            d[q] = dx*dx + dy*dy + dz*dz;
        }
        int keep = 0;
        for (int r = 0; r < KG; r++) {
            float mv = d[0]; int mq = 0;
#pragma unroll
            for (int q = 1; q < 8; q++) if (d[q] < mv) { mv = d[q]; mq = q; }
            int mj = mq * 32 + lane;
#pragma unroll
            for (int off = 16; off; off >>= 1) {
                float ov = __shfl_xor_sync(0xffffffffu, mv, off);
                int   oj = __shfl_xor_sync(0xffffffffu, mj, off);
                if (ov < mv || (ov == mv && oj < mj)) { mv = ov; mj = oj; }
            }
            if (lane == r) keep = mj;
            if ((mj & 31) == lane) {
                int q = mj >> 5;
#pragma unroll
                for (int qq = 0; qq < 8; qq++) if (qq == q) d[qq] = 1e30f;
            }
        }
        g_nbrG[b * NGR + gl][lane] = b * NA + keep;
    } else {
        // ---- weight folding ----
        int pbid = bid - 2232;
        int c = t;
        if (pbid < NL * NGAUSS) {
            int l = pbid / NGAUSS, g = pbid % NGAUSS;
            if (c < EDGEF) sx[c] = edge_W[(l * NGAUSS + g) * EDGEF + c];
            __syncthreads();
            const float* W1c = W1 + l * MIROWS * HID + 2 * CODE * HID;
            float acc = 0.f;
#pragma unroll
            for (int e = 0; e < EDGEF; e++) acc = fmaf(sx[e], W1c[e * HID + c], acc);
            g_EW1[l][g * HID + c] = acc;
        } else if (pbid < NL * NGAUSS + NL) {
            int l = pbid - NL * NGAUSS;
            if (c < EDGEF) sx[c] = edge_b[l * EDGEF + c];
            __syncthreads();
            const float* W1c = W1 + l * MIROWS * HID + 2 * CODE * HID;
            float acc = b1[l * HID + c];
#pragma unroll
            for (int e = 0; e < EDGEF; e++) acc = fmaf(sx[e], W1c[e * HID + c], acc);
            g_b1eff[l][c] = acc;
        } else {
            int l = pbid - NL * NGAUSS - NL;
            if (c < EDGEF) {
                float acc = 0.f;
#pragma unroll
                for (int g = 0; g < NGAUSS; g++)
                    acc = fmaf(gc.g5[g], edge_W[(l * NGAUSS + g) * EDGEF + c], acc);
                sx[c] = acc;
            }
            __syncthreads();
            const float* W1c = W1 + l * MIROWS * HID + 2 * CODE * HID;
            float acc = 0.f;
#pragma unroll
            for (int e = 0; e < EDGEF; e++) acc = fmaf(sx[e], W1c[e * HID + c], acc);
            g_C[l][c] = acc;
        }
    }
}

// ================= k_gauss: per-edge gaussians + clip flags =================
__global__ void __launch_bounds__(256) k_gauss(GaussC gc) {
    int tid = blockIdx.x * 256 + threadIdx.x;
    if (tid >= NEDGE) return;
    int node;
    int* sp;
    float4* dst;
    if (tid < NATOM * KA) {
        node = tid / KA;
        sp = &g_nbrA[node][tid % KA];
        dst = &g_gsA[tid * 5];
    } else {
        int e = tid - NATOM * KA;
        node = NATOM + e / KG;
        sp = &g_nbrG[e / KG][e % KG];
        dst = &g_gsG[e * 5];
    }
    int nbr = *sp;
    float dx = g_npos[nbr*3]   - g_npos[node*3];
    float dy = g_npos[nbr*3+1] - g_npos[node*3+1];
    float dz = g_npos[nbr*3+2] - g_npos[node*3+2];
    float dist = sqrtf(dx*dx + dy*dy + dz*dz);
    if (dist >= 5.0f) { *sp = nbr | CLIPBIT; return; }
    float gv[NGAUSS];
#pragma unroll
    for (int g = 0; g < NGAUSS; g++) {
        float dd = dist - gc.off[g];
        gv[g] = exp2f(gc.coeff2[g] * dd * dd);
    }
    dst[0] = make_float4(gv[0],  gv[1],  gv[2],  gv[3]);
    dst[1] = make_float4(gv[4],  gv[5],  gv[6],  gv[7]);
    dst[2] = make_float4(gv[8],  gv[9],  gv[10], gv[11]);
    dst[3] = make_float4(gv[12], gv[13], gv[14], gv[15]);
    dst[4] = make_float4(gv[16], gv[17], gv[18], gv[19]);
}

// ================= k_proj: Psrc (atoms) + Pdst (all), weight-stationary =================
__global__ void __launch_bounds__(128) k_proj(const float* __restrict__ W1, int l, int cur) {
    int c = threadIdx.x;
    bool srcRole = blockIdx.x >= PD_BLOCKS;
    const float* Wb = W1 + (srcRole ? 0 : CODE * HID);
    float w[CODE];
#pragma unroll
    for (int k = 0; k < CODE; k++) w[k] = Wb[k * HID + c];
    float bias = srcRole ? 0.f : g_b1eff[l][c];
    float* dst = srcRole ? g_Psrc : g_Pdst;
    int nCh = (srcRole ? NATOM : NNODE) / 4;
    int b0 = srcRole ? (blockIdx.x - PD_BLOCKS) : blockIdx.x;
    int nBlk = srcRole ? PS_BLOCKS : PD_BLOCKS;
    __shared__ __align__(16) float hsh[4 * CODE];
    const float* hsrc = g_h[cur];
    for (int ch = b0; ch < nCh; ch += nBlk) {
        int n0 = ch * 4;
        hsh[c]       = hsrc[n0 * CODE + c];
        hsh[c + 128] = hsrc[n0 * CODE + 128 + c];
        __syncthreads();
#pragma unroll
        for (int q = 0; q < 4; q++) {
            float acc = bias;
            const float4* h4 = (const float4*)(hsh + q * CODE);
#pragma unroll
            for (int k4 = 0; k4 < 16; k4++) {
                float4 hv = h4[k4];
                acc = fmaf(hv.x, w[4*k4+0], acc);
                acc = fmaf(hv.y, w[4*k4+1], acc);
                acc = fmaf(hv.z, w[4*k4+2], acc);
                acc = fmaf(hv.w, w[4*k4+3], acc);
            }
            dst[(n0 + q) * HID + c] = acc;
        }
        __syncthreads();
    }
}

// ================= k_edge: stage 1 only, 1 barrier/node, double-buffered staging =================
__device__ __forceinline__ void stage_node(int n, float4 (*sGb)[5], int* sNbrb, int c) {
    bool atom = n < NATOM;
    int k = atom ? KA : KG;
    if (c < k) {
        int jr = atom ? g_nbrA[n][c] : g_nbrG[n - NATOM][c];
        sNbrb[c] = jr;
        if (!(jr & CLIPBIT)) {
            const float4* src = atom ? &g_gsA[(n * KA + c) * 5]
                                     : &g_gsG[((n - NATOM) * KG + c) * 5];
#pragma unroll
            for (int i = 0; i < 5; i++) sGb[c][i] = src[i];
        }
    }
}

__global__ void __launch_bounds__(128, 6) k_edge(int l, int last) {
    __shared__ __align__(16) float4 sG[2][2][KG][5];   // [half][buf]
    __shared__ int sNbr[2][2][KG];

    int t = threadIdx.x, half = t >> 6, c = t & 63;
    int barid = 1 + half;

    u64 ewp0[10], ewp1[10];
    const float* ew = g_EW1[l];
#pragma unroll
    for (int i = 0; i < 10; i++) {
        ewp0[i] = pk(ew[(2*i)*HID + 2*c],     ew[(2*i+1)*HID + 2*c]);
        ewp1[i] = pk(ew[(2*i)*HID + 2*c + 1], ew[(2*i+1)*HID + 2*c + 1]);
    }
    u64 Cp = ((const u64*)g_C[l])[c];

    int nStart = last ? NATOM : 0;
    int nPairs = (NNODE - nStart) >> 1;
    const u64* psrcq = (const u64*)g_Psrc;
    const u64* pdstq = (const u64*)g_Pdst;
    u64* hsq = (u64*)g_HS;

    int p = blockIdx.x;
    if (p >= nPairs) return;
    stage_node(nStart + 2*p + half, sG[half][0], sNbr[half][0], c);
    barhalf(barid);
    int pb = 0;

    for (; p < nPairs; p += gridDim.x) {
        int n = nStart + 2*p + half;
        int pn = p + gridDim.x;
        if (pn < nPairs)
            stage_node(nStart + 2*pn + half, sG[half][pb ^ 1], sNbr[half][pb ^ 1], c);

        bool atom = n < NATOM;
        int k = atom ? KA : KG;
        u64 pd = pdstq[n * 64 + c];
        float hs0 = 0.f, hs1 = 0.f;
        const int* nb_ = sNbr[half][pb];
        for (int j0 = 0; j0 < k; j0 += 4) {
            int nf[4]; u64 ps[4];
#pragma unroll
            for (int m = 0; m < 4; m++) {
                nf[m] = nb_[j0 + m];
                ps[m] = psrcq[(nf[m] & NMASK) * 64 + c];
            }
#pragma unroll
            for (int m = 0; m < 4; m++) {
                u64 bu = add2(pd, ps[m]);
                if (nf[m] & CLIPBIT) {
                    float2 b = upk(add2(bu, Cp));
                    hs0 += fmaxf(b.x, 0.f);
                    hs1 += fmaxf(b.y, 0.f);
                } else {
                    const ulonglong2* gj = (const ulonglong2*)sG[half][pb][j0 + m];
                    u64 A0 = 0ull, A1 = 0ull, B0 = 0ull, B1 = 0ull;
#pragma unroll
                    for (int i2 = 0; i2 < 5; i2++) {
                        ulonglong2 gp = gj[i2];
                        ffma2(A0, gp.x, ewp0[2*i2]);
                        ffma2(B0, gp.x, ewp1[2*i2]);
                        ffma2(A1, gp.y, ewp0[2*i2+1]);
                        ffma2(B1, gp.y, ewp1[2*i2+1]);
                    }
                    float2 b = upk(bu);
                    float2 va = upk(add2(A0, A1)), vb = upk(add2(B0, B1));
                    hs0 += fmaxf(b.x + va.x + va.y, 0.f);
                    hs1 += fmaxf(b.y + vb.x + vb.y, 0.f);
                }
            }
        }
        hsq[n * 64 + c] = pk(hs0, hs1);
        barhalf(barid);
        pb ^= 1;
    }
}

// ================= k_post: aggr = mean(HS)@W2 + residual + LN, W2 register-stationary =================
__global__ void __launch_bounds__(128, 5) k_post(
    const float* __restrict__ W2, const float* __restrict__ b2,
    const float* __restrict__ lng, const float* __restrict__ lnb,
    int cur, int last, float* __restrict__ out)
{
    __shared__ __align__(16) float sHS4[4][HID];
    __shared__ float sPart[2][4][CODE];
    __shared__ float2 sred[4][2];

    int t = threadIdx.x, c = t & 63, h = t >> 6, lane = t & 31, wh = (t >> 5) & 1;

    u64 wk[32];
#pragma unroll
    for (int i = 0; i < 32; i++) {
        int k0 = 64 * h + 2 * i;
        wk[i] = pk(W2[k0 * CODE + c], W2[(k0 + 1) * CODE + c]);
    }
    float b2c = b2[c], gmc = lng[c], bbc = lnb[c];

    int nStart = last ? NATOM : 0;
    int nBatch = (NNODE - nStart) >> 2;
    const float* hcur = g_h[cur];

    for (int bi = blockIdx.x; bi < nBatch; bi += gridDim.x) {
        int base = nStart + bi * 4;
        ((float4*)sHS4)[t] = ((const float4*)(g_HS + (size_t)base * HID))[t];
        __syncthreads();
#pragma unroll
        for (int q = 0; q < 4; q++) {
            const u64* hp = (const u64*)sHS4[q];
            u64 acc = 0ull;
#pragma unroll
            for (int i = 0; i < 32; i++) ffma2(acc, hp[32 * h + i], wk[i]);
            float2 av = upk(acc);
            sPart[h][q][c] = av.x + av.y;
        }
        __syncthreads();
        float xs[2];
#pragma unroll
        for (int qq = 0; qq < 2; qq++) {
            int q = 2 * h + qq;
            int n = base + q;
            float inv = (n < NATOM) ? (1.f / KA) : (1.f / KG);
            float x = (sPart[0][q][c] + sPart[1][q][c]) * inv
                      + __ldg(&hcur[n * CODE + c]) + b2c;
            xs[qq] = x;
            float s1 = x, s2 = x * x;
#pragma unroll
            for (int o = 16; o; o >>= 1) {
                s1 += __shfl_xor_sync(0xffffffffu, s1, o);
                s2 += __shfl_xor_sync(0xffffffffu, s2, o);
            }
            if (lane == 0) sred[q][wh] = make_float2(s1, s2);
        }
        __syncthreads();
#pragma unroll
        for (int qq = 0; qq < 2; qq++) {
            int q = 2 * h + qq;
            int n = base + q;
            float2 ra = sred[q][0], rb = sred[q][1];
            float mu  = (ra.x + rb.x) * (1.f / CODE);
            float var = (ra.y + rb.y) * (1.f / CODE) - mu * mu;
            float y = (xs[qq] - mu) * rsqrtf(var + 1e-5f) * gmc + bbc;
            if (last) out[(n - NATOM) * CODE + c] = y;
            else      g_h[cur ^ 1][n * CODE + c] = y;
        }
    }
}

// ---------------- launch ----------------
extern "C" void kernel_launch(void* const* d_in, const int* in_sizes, int n_in,
                              void* d_out, int out_size) {
    const float* pos    = (const float*)d_in[0];
    const int*   atype  = (const int*)  d_in[1];
    const float* edge_W = (const float*)d_in[3];
    const float* edge_b = (const float*)d_in[4];
    const float* W1     = (const float*)d_in[5];
    const float* b1     = (const float*)d_in[6];
    const float* W2     = (const float*)d_in[7];
    const float* b2     = (const float*)d_in[8];
    const float* lng    = (const float*)d_in[9];
    const float* lnb    = (const float*)d_in[10];
    float* out = (float*)d_out;

    GaussC gc;
    {
        double off[NGAUSS], dd[NGAUSS];
        double hi = log(6.0);
        for (int g = 0; g < NGAUSS; g++) off[g] = exp(hi * (double)g / 19.0) - 1.0;
        for (int g = NGAUSS - 1; g >= 1; g--) dd[g] = off[g] - off[g-1];
        dd[0] = dd[1];
        for (int g = 0; g < NGAUSS; g++) {
            double coeff = -0.5 / (dd[g] * dd[g]);
            gc.off[g]    = (float)off[g];
            gc.coeff2[g] = (float)(coeff * 1.4426950408889634);
            double d5 = 5.0 - off[g];
            gc.g5[g]   = (float)exp(coeff * d5 * d5);
        }
    }

    k_setup<<<2232 + NL*NGAUSS + 2*NL, 128>>>(pos, atype, edge_W, edge_b, W1, b1, gc);
    k_gauss<<<(NEDGE + 255) / 256, 256>>>(gc);

    int cur = 0;
    for (int l = 0; l < NL; l++) {
        int last = (l == NL - 1) ? 1 : 0;
        k_proj<<<PD_BLOCKS + PS_BLOCKS, 128>>>(W1 + l*MIROWS*HID, l, cur);
        k_edge<<<EDGE_BLOCKS, 128>>>(l, last);
        k_post<<<POST_BLOCKS, 128>>>(W2 + l*HID*CODE, b2 + l*CODE,
                                     lng + l*CODE, lnb + l*CODE,
                                     cur, last, out);
        cur ^= 1;
    }
}

// round 6
// speedup vs baseline: 1.0825x; 1.0825x over previous
#include <cuda_runtime.h>
#include <math.h>

typedef unsigned long long u64;

#define NB 4
#define NA 256
#define GSZ 12
#define NGR 1728
#define KA 8
#define KG 32
#define NL 4
#define CODE 64
#define HID 128
#define EDGEF 64
#define NGAUSS 20
#define NATOM (NB*NA)          // 1024
#define NGRID (NB*NGR)         // 6912
#define NNODE (NATOM+NGRID)    // 7936
#define MIROWS (2*CODE+EDGEF)  // 192

#define PD_BLOCKS 256
#define PS_BLOCKS 40
#define EDGE_BLOCKS 740
#define CLIPBIT (1 << 30)
#define NMASK 0xFFFF
#define NEDGE (NATOM*KA + NGRID*KG)   // 229376

// ---------------- static device scratch ----------------
__device__ float g_h[2][NNODE*CODE];
__device__ float g_npos[NNODE*3];
__device__ int   g_nbrA[NATOM][KA];
__device__ int   g_nbrG[NGRID][KG];
__device__ float4 g_gsA[NATOM*KA*5];
__device__ float4 g_gsG[NGRID*KG*5];
__device__ float g_Psrc[NATOM*HID];
__device__ float g_Pdst[NNODE*HID];
__device__ float g_EW1[NL][NGAUSS*HID];
__device__ float g_b1eff[NL][HID];
__device__ float g_C[NL][HID];
__device__ float4 g_W2q[NL][32*CODE];

struct GaussC { float off[NGAUSS]; float coeff2[NGAUSS]; float g5[NGAUSS]; };

// ---------------- f32x2 helpers ----------------
__device__ __forceinline__ void ffma2(u64 &d, u64 a, u64 b) {
    asm("fma.rn.f32x2 %0, %1, %2, %0;" : "+l"(d) : "l"(a), "l"(b));
}
__device__ __forceinline__ u64 add2(u64 a, u64 b) {
    u64 r; asm("add.rn.f32x2 %0, %1, %2;" : "=l"(r) : "l"(a), "l"(b)); return r;
}
__device__ __forceinline__ u64 pk(float x, float y) {
    u64 r; asm("mov.b64 %0, {%1, %2};" : "=l"(r) : "f"(x), "f"(y)); return r;
}
__device__ __forceinline__ float2 upk(u64 v) {
    float2 r; asm("mov.b64 {%0, %1}, %2;" : "=f"(r.x), "=f"(r.y) : "l"(v)); return r;
}
__device__ __forceinline__ void barhalf(int id) {
    asm volatile("bar.sync %0, %1;" :: "r"(id), "r"(64) : "memory");
}

// ================= k_setup: init + knn_a + knn_g + prep, one launch =================
__global__ void __launch_bounds__(128) k_setup(
    const float* __restrict__ pos, const int* __restrict__ atype,
    const float* __restrict__ edge_W, const float* __restrict__ edge_b,
    const float* __restrict__ W1, const float* __restrict__ b1,
    const float* __restrict__ W2, GaussC gc)
{
    __shared__ float sx[NA], sy[NA], sz[NA];
    int bid = blockIdx.x, t = threadIdx.x;

    if (bid < 248) {
        for (int i = bid * 128 + t; i < NNODE * CODE; i += 248 * 128) {
            int n = i >> 6, c = i & 63;
            g_h[0][i] = (n < NATOM && c == atype[n]) ? 1.f : 0.f;
        }
        for (int i = bid * 128 + t; i < NNODE; i += 248 * 128) {
            float x, y, z;
            if (i < NATOM) { x = pos[i*3]; y = pos[i*3+1]; z = pos[i*3+2]; }
            else {
                int g = (i - NATOM) % NGR;
                int ix = g / (GSZ*GSZ), iy = (g / GSZ) % GSZ, iz = g % GSZ;
                x = -8.25f + 1.5f*ix; y = -8.25f + 1.5f*iy; z = -8.25f + 1.5f*iz;
            }
            g_npos[i*3] = x; g_npos[i*3+1] = y; g_npos[i*3+2] = z;
        }
    } else if (bid < 248 + 256) {
        // ---- atom kNN (warp per node, stable ties) ----
        int abid = bid - 248;
        int lane = t & 31, w = t >> 5;
        int b = (abid * 4) / NA;
        for (int j = t; j < NA; j += 128) {
            int gj = b * NA + j;
            sx[j] = pos[gj*3]; sy[j] = pos[gj*3+1]; sz[j] = pos[gj*3+2];
        }
        __syncthreads();
        int il = (abid * 4 + w) % NA;
        float px = sx[il], py = sy[il], pz = sz[il];
        float d[8];
#pragma unroll
        for (int q = 0; q < 8; q++) {
            int j = q * 32 + lane;
            float dx = sx[j]-px, dy = sy[j]-py, dz = sz[j]-pz;
            float dd = dx*dx + dy*dy + dz*dz;
            d[q] = (j == il) ? 1e30f : dd;
        }
        int keep = 0;
        for (int r = 0; r < KA; r++) {
            float mv = d[0]; int mq = 0;
#pragma unroll
            for (int q = 1; q < 8; q++) if (d[q] < mv) { mv = d[q]; mq = q; }
            int mj = mq * 32 + lane;
#pragma unroll
            for (int off = 16; off; off >>= 1) {
                float ov = __shfl_xor_sync(0xffffffffu, mv, off);
                int   oj = __shfl_xor_sync(0xffffffffu, mj, off);
                if (ov < mv || (ov == mv && oj < mj)) { mv = ov; mj = oj; }
            }
            if (lane == r) keep = mj;
            if ((mj & 31) == lane) {
                int q = mj >> 5;
#pragma unroll
                for (int qq = 0; qq < 8; qq++) if (qq == q) d[qq] = 1e30f;
            }
        }
        if (lane < KA) g_nbrA[b * NA + il][lane] = b * NA + keep;
    } else if (bid < 248 + 256 + 1728) {
        // ---- grid kNN ----
        int gbid = bid - 504;
        int lane = t & 31, w = t >> 5;
        int b = (gbid * 4) / NGR;
        for (int j = t; j < NA; j += 128) {
            int gj = b * NA + j;
            sx[j] = pos[gj*3]; sy[j] = pos[gj*3+1]; sz[j] = pos[gj*3+2];
        }
        __syncthreads();
        int gl = (gbid * 4 + w) % NGR;
        int ix = gl / (GSZ*GSZ), iy = (gl / GSZ) % GSZ, iz = gl % GSZ;
        float px = -8.25f + 1.5f*ix, py = -8.25f + 1.5f*iy, pz = -8.25f + 1.5f*iz;
        float d[8];
#pragma unroll
        for (int q = 0; q < 8; q++) {
            int j = q * 32 + lane;
            float dx = sx[j]-px, dy = sy[j]-py, dz = sz[j]-pz;
            d[q] = dx*dx + dy*dy + dz*dz;
        }
        int keep = 0;
        for (int r = 0; r < KG; r++) {
            float mv = d[0]; int mq = 0;
#pragma unroll
            for (int q = 1; q < 8; q++) if (d[q] < mv) { mv = d[q]; mq = q; }
            int mj = mq * 32 + lane;
#pragma unroll
            for (int off = 16; off; off >>= 1) {
                float ov = __shfl_xor_sync(0xffffffffu, mv, off);
                int   oj = __shfl_xor_sync(0xffffffffu, mj, off);
                if (ov < mv || (ov == mv && oj < mj)) { mv = ov; mj = oj; }
            }
            if (lane == r) keep = mj;
            if ((mj & 31) == lane) {
                int q = mj >> 5;
#pragma unroll
                for (int qq = 0; qq < 8; qq++) if (qq == q) d[qq] = 1e30f;
            }
        }
        g_nbrG[b * NGR + gl][lane] = b * NA + keep;
    } else {
        // ---- weight folding ----
        int pbid = bid - 2232;
        int c = t;
        if (pbid < NL * NGAUSS) {
            int l = pbid / NGAUSS, g = pbid % NGAUSS;
            if (c < EDGEF) sx[c] = edge_W[(l * NGAUSS + g) * EDGEF + c];
            __syncthreads();
            const float* W1c = W1 + l * MIROWS * HID + 2 * CODE * HID;
            float acc = 0.f;
#pragma unroll
            for (int e = 0; e < EDGEF; e++) acc = fmaf(sx[e], W1c[e * HID + c], acc);
            g_EW1[l][g * HID + c] = acc;
        } else if (pbid < NL * NGAUSS + NL) {
            int l = pbid - NL * NGAUSS;
            if (c < EDGEF) sx[c] = edge_b[l * EDGEF + c];
            __syncthreads();
            const float* W1c = W1 + l * MIROWS * HID + 2 * CODE * HID;
            float acc = b1[l * HID + c];
#pragma unroll
            for (int e = 0; e < EDGEF; e++) acc = fmaf(sx[e], W1c[e * HID + c], acc);
            g_b1eff[l][c] = acc;
        } else if (pbid < NL * NGAUSS + 2 * NL) {
            int l = pbid - NL * NGAUSS - NL;
            if (c < EDGEF) {
                float acc = 0.f;
#pragma unroll
                for (int g = 0; g < NGAUSS; g++)
                    acc = fmaf(gc.g5[g], edge_W[(l * NGAUSS + g) * EDGEF + c], acc);
                sx[c] = acc;
            }
            __syncthreads();
            const float* W1c = W1 + l * MIROWS * HID + 2 * CODE * HID;
            float acc = 0.f;
#pragma unroll
            for (int e = 0; e < EDGEF; e++) acc = fmaf(sx[e], W1c[e * HID + c], acc);
            g_C[l][c] = acc;
        } else {
            int l = pbid - NL * NGAUSS - 2 * NL;
            const float* W2l = W2 + l * HID * CODE;
            for (int idx = c; idx < 32 * CODE; idx += 128) {
                int k4 = idx / CODE, cc = idx % CODE;
                g_W2q[l][idx] = make_float4(W2l[(4*k4+0)*CODE + cc], W2l[(4*k4+1)*CODE + cc],
                                            W2l[(4*k4+2)*CODE + cc], W2l[(4*k4+3)*CODE + cc]);
            }
        }
    }
}

// ================= k_gauss: per-edge gaussians + clip flags =================
__global__ void __launch_bounds__(256) k_gauss(GaussC gc) {
    int tid = blockIdx.x * 256 + threadIdx.x;
    if (tid >= NEDGE) return;
    int node;
    int* sp;
    float4* dst;
    if (tid < NATOM * KA) {
        node = tid / KA;
        sp = &g_nbrA[node][tid % KA];
        dst = &g_gsA[tid * 5];
    } else {
        int e = tid - NATOM * KA;
        node = NATOM + e / KG;
        sp = &g_nbrG[e / KG][e % KG];
        dst = &g_gsG[e * 5];
    }
    int nbr = *sp;
    float dx = g_npos[nbr*3]   - g_npos[node*3];
    float dy = g_npos[nbr*3+1] - g_npos[node*3+1];
    float dz = g_npos[nbr*3+2] - g_npos[node*3+2];
    float dist = sqrtf(dx*dx + dy*dy + dz*dz);
    if (dist >= 5.0f) { *sp = nbr | CLIPBIT; return; }
    float gv[NGAUSS];
#pragma unroll
    for (int g = 0; g < NGAUSS; g++) {
        float dd = dist - gc.off[g];
        gv[g] = exp2f(gc.coeff2[g] * dd * dd);
    }
    dst[0] = make_float4(gv[0],  gv[1],  gv[2],  gv[3]);
    dst[1] = make_float4(gv[4],  gv[5],  gv[6],  gv[7]);
    dst[2] = make_float4(gv[8],  gv[9],  gv[10], gv[11]);
    dst[3] = make_float4(gv[12], gv[13], gv[14], gv[15]);
    dst[4] = make_float4(gv[16], gv[17], gv[18], gv[19]);
}

// ================= k_proj: Psrc (atoms) + Pdst (all), weight-stationary =================
__global__ void __launch_bounds__(128) k_proj(const float* __restrict__ W1, int l, int cur) {
    int c = threadIdx.x;
    bool srcRole = blockIdx.x >= PD_BLOCKS;
    const float* Wb = W1 + (srcRole ? 0 : CODE * HID);
    float w[CODE];
#pragma unroll
    for (int k = 0; k < CODE; k++) w[k] = Wb[k * HID + c];
    float bias = srcRole ? 0.f : g_b1eff[l][c];
    float* dst = srcRole ? g_Psrc : g_Pdst;
    int nCh = (srcRole ? NATOM : NNODE) / 4;
    int b0 = srcRole ? (blockIdx.x - PD_BLOCKS) : blockIdx.x;
    int nBlk = srcRole ? PS_BLOCKS : PD_BLOCKS;
    __shared__ __align__(16) float hsh[4 * CODE];
    const float* hsrc = g_h[cur];
    for (int ch = b0; ch < nCh; ch += nBlk) {
        int n0 = ch * 4;
        hsh[c]       = hsrc[n0 * CODE + c];
        hsh[c + 128] = hsrc[n0 * CODE + 128 + c];
        __syncthreads();
#pragma unroll
        for (int q = 0; q < 4; q++) {
            float acc = bias;
            const float4* h4 = (const float4*)(hsh + q * CODE);
#pragma unroll
            for (int k4 = 0; k4 < 16; k4++) {
                float4 hv = h4[k4];
                acc = fmaf(hv.x, w[4*k4+0], acc);
                acc = fmaf(hv.y, w[4*k4+1], acc);
                acc = fmaf(hv.z, w[4*k4+2], acc);
                acc = fmaf(hv.w, w[4*k4+3], acc);
            }
            dst[(n0 + q) * HID + c] = acc;
        }
        __syncthreads();
    }
}

// ================= k_edge: fused, double-buffered staging, 2 barriers/node =================
__device__ __forceinline__ void stage_node(int n, float4 (*sGb)[5], int* sNbrb, int c) {
    bool atom = n < NATOM;
    int k = atom ? KA : KG;
    if (c < k) {
        int jr = atom ? g_nbrA[n][c] : g_nbrG[n - NATOM][c];
        sNbrb[c] = jr;
        if (!(jr & CLIPBIT)) {
            const float4* src = atom ? &g_gsA[(n * KA + c) * 5]
                                     : &g_gsG[((n - NATOM) * KG + c) * 5];
#pragma unroll
            for (int i = 0; i < 5; i++) sGb[c][i] = src[i];
        }
    }
}

__global__ void __launch_bounds__(128, 5) k_edge(
    const float* __restrict__ b2, const float* __restrict__ lng,
    const float* __restrict__ lnb, int l, int cur, int last,
    float* __restrict__ out)
{
    __shared__ __align__(16) float4 sW2[32 * CODE];        // 32KB
    __shared__ __align__(16) float4 sG[2][2][KG][5];       // 10KB [half][buf]
    __shared__ int    sNbr[2][2][KG];
    __shared__ __align__(16) float sHS[2][HID];
    __shared__ float2 sred[2][2];

    int t = threadIdx.x;
    int half = t >> 6, c = t & 63, lane = t & 31, hw = (t >> 5) & 1;
    int barid = 1 + half;

    for (int i = t; i < 32 * CODE; i += 128) sW2[i] = g_W2q[l][i];

    u64 ewp0[10], ewp1[10];
    const float* ew = g_EW1[l];
#pragma unroll
    for (int i = 0; i < 10; i++) {
        ewp0[i] = pk(ew[(2*i)*HID + 2*c],     ew[(2*i+1)*HID + 2*c]);
        ewp1[i] = pk(ew[(2*i)*HID + 2*c + 1], ew[(2*i+1)*HID + 2*c + 1]);
    }
    u64 Cp = ((const u64*)g_C[l])[c];
    float b2c = b2[c], gmc = lng[c], bbc = lnb[c];

    int nStart = last ? NATOM : 0;
    int nPairs = (NNODE - nStart) >> 1;
    const u64* psrcq = (const u64*)g_Psrc;
    const u64* pdstq = (const u64*)g_Pdst;
    const float* hcur = g_h[cur];

    int p0 = blockIdx.x;
    if (p0 < nPairs)
        stage_node(nStart + 2*p0 + half, sG[half][0], sNbr[half][0], c);
    __syncthreads();     // covers sW2 + initial staging
    int pb = 0;

    for (int p = p0; p < nPairs; p += gridDim.x) {
        int n = nStart + 2*p + half;

        // prefetch-stage next node into the other buffer (overlaps with stage-1 below)
        int pn = p + gridDim.x;
        if (pn < nPairs)
            stage_node(nStart + 2*pn + half, sG[half][pb ^ 1], sNbr[half][pb ^ 1], c);
        float hres = __ldg(&hcur[n * CODE + c]);

        bool atom = n < NATOM;
        int k = atom ? KA : KG;
        u64 pd = pdstq[n * 64 + c];
        float hs0 = 0.f, hs1 = 0.f;
        const int* nb_ = sNbr[half][pb];
        for (int j0 = 0; j0 < k; j0 += 8) {
            int nf[8]; u64 ps[8];
#pragma unroll
            for (int m = 0; m < 8; m++) {
                nf[m] = nb_[j0 + m];
                ps[m] = psrcq[(nf[m] & NMASK) * 64 + c];
            }
#pragma unroll
            for (int m = 0; m < 8; m++) {
                u64 bu = add2(pd, ps[m]);
                if (nf[m] & CLIPBIT) {
                    float2 b = upk(add2(bu, Cp));
                    hs0 += fmaxf(b.x, 0.f);
                    hs1 += fmaxf(b.y, 0.f);
                } else {
                    const ulonglong2* gj = (const ulonglong2*)sG[half][pb][j0 + m];
                    u64 A0 = 0ull, A1 = 0ull, B0 = 0ull, B1 = 0ull;
#pragma unroll
                    for (int i2 = 0; i2 < 5; i2++) {
                        ulonglong2 gp = gj[i2];
                        ffma2(A0, gp.x, ewp0[2*i2]);
                        ffma2(B0, gp.x, ewp1[2*i2]);
                        ffma2(A1, gp.y, ewp0[2*i2+1]);
                        ffma2(B1, gp.y, ewp1[2*i2+1]);
                    }
                    float2 b = upk(bu);
                    float2 va = upk(add2(A0, A1)), vb = upk(add2(B0, B1));
                    hs0 += fmaxf(b.x + va.x + va.y, 0.f);
                    hs1 += fmaxf(b.y + vb.x + vb.y, 0.f);
                }
            }
        }
        ((float2*)sHS[half])[c] = make_float2(hs0, hs1);
        barhalf(barid);                       // (B) sHS ready

        // ---- stage 2: aggr = mean(hidden) @ W2 from smem ----
        u64 acc0 = 0ull, acc1 = 0ull;
        const ulonglong2* hq = (const ulonglong2*)sHS[half];
#pragma unroll 8
        for (int k4 = 0; k4 < 32; k4++) {
            ulonglong2 hv = hq[k4];
            ulonglong2 wv = *(const ulonglong2*)&sW2[k4 * CODE + c];
            ffma2(acc0, hv.x, wv.x);
            ffma2(acc1, hv.y, wv.y);
        }
        float2 a0 = upk(acc0), a1 = upk(acc1);
        float x = hres + (a0.x + a0.y + a1.x + a1.y) * (atom ? (1.f/KA) : (1.f/KG)) + b2c;

        // ---- single-pass LN ----
        float s1 = x, s2 = x * x;
#pragma unroll
        for (int off = 16; off; off >>= 1) {
            s1 += __shfl_xor_sync(0xffffffffu, s1, off);
            s2 += __shfl_xor_sync(0xffffffffu, s2, off);
        }
        if (lane == 0) sred[half][hw] = make_float2(s1, s2);
        barhalf(barid);                       // (C) sred ready; also joins staging of next
        float2 ra = sred[half][0], rb = sred[half][1];
        float mu  = (ra.x + rb.x) * (1.f / CODE);
        float var = (ra.y + rb.y) * (1.f / CODE) - mu * mu;
        float y = (x - mu) * rsqrtf(var + 1e-5f) * gmc + bbc;
        if (last) out[(n - NATOM) * CODE + c] = y;
        else      g_h[cur ^ 1][n * CODE + c] = y;
        pb ^= 1;
    }
}

// ---------------- launch ----------------
extern "C" void kernel_launch(void* const* d_in, const int* in_sizes, int n_in,
                              void* d_out, int out_size) {
    const float* pos    = (const float*)d_in[0];
    const int*   atype  = (const int*)  d_in[1];
    const float* edge_W = (const float*)d_in[3];
    const float* edge_b = (const float*)d_in[4];
    const float* W1     = (const float*)d_in[5];
    const float* b1     = (const float*)d_in[6];
    const float* W2     = (const float*)d_in[7];
    const float* b2     = (const float*)d_in[8];
    const float* lng    = (const float*)d_in[9];
    const float* lnb    = (const float*)d_in[10];
    float* out = (float*)d_out;

    GaussC gc;
    {
        double off[NGAUSS], dd[NGAUSS];
        double hi = log(6.0);
        for (int g = 0; g < NGAUSS; g++) off[g] = exp(hi * (double)g / 19.0) - 1.0;
        for (int g = NGAUSS - 1; g >= 1; g--) dd[g] = off[g] - off[g-1];
        dd[0] = dd[1];
        for (int g = 0; g < NGAUSS; g++) {
            double coeff = -0.5 / (dd[g] * dd[g]);
            gc.off[g]    = (float)off[g];
            gc.coeff2[g] = (float)(coeff * 1.4426950408889634);
            double d5 = 5.0 - off[g];
            gc.g5[g]   = (float)exp(coeff * d5 * d5);
        }
    }

    k_setup<<<2232 + NL*NGAUSS + 3*NL, 128>>>(pos, atype, edge_W, edge_b, W1, b1, W2, gc);
    k_gauss<<<(NEDGE + 255) / 256, 256>>>(gc);

    int cur = 0;
    for (int l = 0; l < NL; l++) {
        int last = (l == NL - 1) ? 1 : 0;
        k_proj<<<PD_BLOCKS + PS_BLOCKS, 128>>>(W1 + l*MIROWS*HID, l, cur);
        k_edge<<<EDGE_BLOCKS, 128>>>(b2 + l*CODE, lng + l*CODE, lnb + l*CODE,
                                     l, cur, last, out);
        cur ^= 1;
    }
}

// round 7
// speedup vs baseline: 1.2379x; 1.1436x over previous
#include <cuda_runtime.h>
#include <math.h>

typedef unsigned long long u64;

#define NB 4
#define NA 256
#define GSZ 12
#define NGR 1728
#define KA 8
#define KG 32
#define NL 4
#define CODE 64
#define HID 128
#define EDGEF 64
#define NGAUSS 20
#define NATOM (NB*NA)          // 1024
#define NGRID (NB*NGR)         // 6912
#define NNODE (NATOM+NGRID)    // 7936
#define MIROWS (2*CODE+EDGEF)  // 192

#define PD_BLOCKS 256
#define PS_BLOCKS 40
#define CLIPBIT (1 << 30)
#define NMASK 0xFFFF
#define NEDGE (NATOM*KA + NGRID*KG)   // 229376

// chunked scheduling for k_edge
#define APAIRS (NATOM/2)       // 512
#define GPAIRS (NGRID/2)       // 3456
#define ACHUNK 24
#define GCHUNK 6
#define ABLK ((APAIRS + ACHUNK - 1) / ACHUNK)   // 22
#define GBLK ((GPAIRS + GCHUNK - 1) / GCHUNK)   // 576
#define EDGE_BLOCKS (ABLK + GBLK)               // 598

// ---------------- static device scratch ----------------
__device__ float g_h[2][NNODE*CODE];
__device__ float g_npos[NNODE*3];
__device__ int   g_nbrA[NATOM][KA];
__device__ int   g_nbrG[NGRID][KG];
__device__ float4 g_gsA[NATOM*KA*5];
__device__ float4 g_gsG[NGRID*KG*5];
__device__ float g_Psrc[NATOM*HID];
__device__ float g_Pdst[NNODE*HID];
__device__ float g_EW1[NL][NGAUSS*HID];
__device__ float g_b1eff[NL][HID];
__device__ float g_C[NL][HID];
__device__ float4 g_W2q[NL][32*CODE];

struct GaussC { float off[NGAUSS]; float coeff2[NGAUSS]; float g5[NGAUSS]; };

// ---------------- f32x2 helpers ----------------
__device__ __forceinline__ void ffma2(u64 &d, u64 a, u64 b) {
    asm("fma.rn.f32x2 %0, %1, %2, %0;" : "+l"(d) : "l"(a), "l"(b));
}
__device__ __forceinline__ u64 add2(u64 a, u64 b) {
    u64 r; asm("add.rn.f32x2 %0, %1, %2;" : "=l"(r) : "l"(a), "l"(b)); return r;
}
__device__ __forceinline__ u64 pk(float x, float y) {
    u64 r; asm("mov.b64 %0, {%1, %2};" : "=l"(r) : "f"(x), "f"(y)); return r;
}
__device__ __forceinline__ float2 upk(u64 v) {
    float2 r; asm("mov.b64 {%0, %1}, %2;" : "=f"(r.x), "=f"(r.y) : "l"(v)); return r;
}
__device__ __forceinline__ void barhalf(int id) {
    asm volatile("bar.sync %0, %1;" :: "r"(id), "r"(64) : "memory");
}

// ================= k_setup: init + knn_a + knn_g + prep, one launch =================
__global__ void __launch_bounds__(128) k_setup(
    const float* __restrict__ pos, const int* __restrict__ atype,
    const float* __restrict__ edge_W, const float* __restrict__ edge_b,
    const float* __restrict__ W1, const float* __restrict__ b1,
    const float* __restrict__ W2, GaussC gc)
{
    __shared__ float sx[NA], sy[NA], sz[NA];
    int bid = blockIdx.x, t = threadIdx.x;

    if (bid < 248) {
        for (int i = bid * 128 + t; i < NNODE * CODE; i += 248 * 128) {
            int n = i >> 6, c = i & 63;
            g_h[0][i] = (n < NATOM && c == atype[n]) ? 1.f : 0.f;
        }
        for (int i = bid * 128 + t; i < NNODE; i += 248 * 128) {
            float x, y, z;
            if (i < NATOM) { x = pos[i*3]; y = pos[i*3+1]; z = pos[i*3+2]; }
            else {
                int g = (i - NATOM) % NGR;
                int ix = g / (GSZ*GSZ), iy = (g / GSZ) % GSZ, iz = g % GSZ;
                x = -8.25f + 1.5f*ix; y = -8.25f + 1.5f*iy; z = -8.25f + 1.5f*iz;
            }
            g_npos[i*3] = x; g_npos[i*3+1] = y; g_npos[i*3+2] = z;
        }
    } else if (bid < 248 + 256) {
        // ---- atom kNN (warp per node, stable ties) ----
        int abid = bid - 248;
        int lane = t & 31, w = t >> 5;
        int b = (abid * 4) / NA;
        for (int j = t; j < NA; j += 128) {
            int gj = b * NA + j;
            sx[j] = pos[gj*3]; sy[j] = pos[gj*3+1]; sz[j] = pos[gj*3+2];
        }
        __syncthreads();
        int il = (abid * 4 + w) % NA;
        float px = sx[il], py = sy[il], pz = sz[il];
        float d[8];
#pragma unroll
        for (int q = 0; q < 8; q++) {
            int j = q * 32 + lane;
            float dx = sx[j]-px, dy = sy[j]-py, dz = sz[j]-pz;
            float dd = dx*dx + dy*dy + dz*dz;
            d[q] = (j == il) ? 1e30f : dd;
        }
        int keep = 0;
        for (int r = 0; r < KA; r++) {
            float mv = d[0]; int mq = 0;
#pragma unroll
            for (int q = 1; q < 8; q++) if (d[q] < mv) { mv = d[q]; mq = q; }
            int mj = mq * 32 + lane;
#pragma unroll
            for (int off = 16; off; off >>= 1) {
                float ov = __shfl_xor_sync(0xffffffffu, mv, off);
                int   oj = __shfl_xor_sync(0xffffffffu, mj, off);
                if (ov < mv || (ov == mv && oj < mj)) { mv = ov; mj = oj; }
            }
            if (lane == r) keep = mj;
            if ((mj & 31) == lane) {
                int q = mj >> 5;
#pragma unroll
                for (int qq = 0; qq < 8; qq++) if (qq == q) d[qq] = 1e30f;
            }
        }
        if (lane < KA) g_nbrA[b * NA + il][lane] = b * NA + keep;
    } else if (bid < 248 + 256 + 1728) {
        // ---- grid kNN ----
        int gbid = bid - 504;
        int lane = t & 31, w = t >> 5;
        int b = (gbid * 4) / NGR;
        for (int j = t; j < NA; j += 128) {
            int gj = b * NA + j;
            sx[j] = pos[gj*3]; sy[j] = pos[gj*3+1]; sz[j] = pos[gj*3+2];
        }
        __syncthreads();
        int gl = (gbid * 4 + w) % NGR;
        int ix = gl / (GSZ*GSZ), iy = (gl / GSZ) % GSZ, iz = gl % GSZ;
        float px = -8.25f + 1.5f*ix, py = -8.25f + 1.5f*iy, pz = -8.25f + 1.5f*iz;
        float d[8];
#pragma unroll
        for (int q = 0; q < 8; q++) {
            int j = q * 32 + lane;
            float dx = sx[j]-px, dy = sy[j]-py, dz = sz[j]-pz;
            d[q] = dx*dx + dy*dy + dz*dz;
        }
        int keep = 0;
        for (int r = 0; r < KG; r++) {
            float mv = d[0]; int mq = 0;
#pragma unroll
            for (int q = 1; q < 8; q++) if (d[q] < mv) { mv = d[q]; mq = q; }
            int mj = mq * 32 + lane;
#pragma unroll
            for (int off = 16; off; off >>= 1) {
                float ov = __shfl_xor_sync(0xffffffffu, mv, off);
                int   oj = __shfl_xor_sync(0xffffffffu, mj, off);
                if (ov < mv || (ov == mv && oj < mj)) { mv = ov; mj = oj; }
            }
            if (lane == r) keep = mj;
            if ((mj & 31) == lane) {
                int q = mj >> 5;
#pragma unroll
                for (int qq = 0; qq < 8; qq++) if (qq == q) d[qq] = 1e30f;
            }
        }
        g_nbrG[b * NGR + gl][lane] = b * NA + keep;
    } else {
        // ---- weight folding ----
        int pbid = bid - 2232;
        int c = t;
        if (pbid < NL * NGAUSS) {
            int l = pbid / NGAUSS, g = pbid % NGAUSS;
            if (c < EDGEF) sx[c] = edge_W[(l * NGAUSS + g) * EDGEF + c];
            __syncthreads();
            const float* W1c = W1 + l * MIROWS * HID + 2 * CODE * HID;
            float acc = 0.f;
#pragma unroll
            for (int e = 0; e < EDGEF; e++) acc = fmaf(sx[e], W1c[e * HID + c], acc);
            g_EW1[l][g * HID + c] = acc;
        } else if (pbid < NL * NGAUSS + NL) {
            int l = pbid - NL * NGAUSS;
            if (c < EDGEF) sx[c] = edge_b[l * EDGEF + c];
            __syncthreads();
            const float* W1c = W1 + l * MIROWS * HID + 2 * CODE * HID;
            float acc = b1[l * HID + c];
#pragma unroll
            for (int e = 0; e < EDGEF; e++) acc = fmaf(sx[e], W1c[e * HID + c], acc);
            g_b1eff[l][c] = acc;
        } else if (pbid < NL * NGAUSS + 2 * NL) {
            int l = pbid - NL * NGAUSS - NL;
            if (c < EDGEF) {
                float acc = 0.f;
#pragma unroll
                for (int g = 0; g < NGAUSS; g++)
                    acc = fmaf(gc.g5[g], edge_W[(l * NGAUSS + g) * EDGEF + c], acc);
                sx[c] = acc;
            }
            __syncthreads();
            const float* W1c = W1 + l * MIROWS * HID + 2 * CODE * HID;
            float acc = 0.f;
#pragma unroll
            for (int e = 0; e < EDGEF; e++) acc = fmaf(sx[e], W1c[e * HID + c], acc);
            g_C[l][c] = acc;
        } else {
            int l = pbid - NL * NGAUSS - 2 * NL;
            const float* W2l = W2 + l * HID * CODE;
            for (int idx = c; idx < 32 * CODE; idx += 128) {
                int k4 = idx / CODE, cc = idx % CODE;
                g_W2q[l][idx] = make_float4(W2l[(4*k4+0)*CODE + cc], W2l[(4*k4+1)*CODE + cc],
                                            W2l[(4*k4+2)*CODE + cc], W2l[(4*k4+3)*CODE + cc]);
            }
        }
    }
}

// ================= k_gauss: per-edge gaussians + clip flags =================
__global__ void __launch_bounds__(256) k_gauss(GaussC gc) {
    int tid = blockIdx.x * 256 + threadIdx.x;
    if (tid >= NEDGE) return;
    int node;
    int* sp;
    float4* dst;
    if (tid < NATOM * KA) {
        node = tid / KA;
        sp = &g_nbrA[node][tid % KA];
        dst = &g_gsA[tid * 5];
    } else {
        int e = tid - NATOM * KA;
        node = NATOM + e / KG;
        sp = &g_nbrG[e / KG][e % KG];
        dst = &g_gsG[e * 5];
    }
    int nbr = *sp;
    float dx = g_npos[nbr*3]   - g_npos[node*3];
    float dy = g_npos[nbr*3+1] - g_npos[node*3+1];
    float dz = g_npos[nbr*3+2] - g_npos[node*3+2];
    float dist = sqrtf(dx*dx + dy*dy + dz*dz);
    if (dist >= 5.0f) { *sp = nbr | CLIPBIT; return; }
    float gv[NGAUSS];
#pragma unroll
    for (int g = 0; g < NGAUSS; g++) {
        float dd = dist - gc.off[g];
        gv[g] = exp2f(gc.coeff2[g] * dd * dd);
    }
    dst[0] = make_float4(gv[0],  gv[1],  gv[2],  gv[3]);
    dst[1] = make_float4(gv[4],  gv[5],  gv[6],  gv[7]);
    dst[2] = make_float4(gv[8],  gv[9],  gv[10], gv[11]);
    dst[3] = make_float4(gv[12], gv[13], gv[14], gv[15]);
    dst[4] = make_float4(gv[16], gv[17], gv[18], gv[19]);
}

// ================= k_proj: Psrc (atoms) + Pdst (all), weight-stationary =================
__global__ void __launch_bounds__(128) k_proj(const float* __restrict__ W1, int l, int cur) {
    int c = threadIdx.x;
    bool srcRole = blockIdx.x >= PD_BLOCKS;
    const float* Wb = W1 + (srcRole ? 0 : CODE * HID);
    float w[CODE];
#pragma unroll
    for (int k = 0; k < CODE; k++) w[k] = Wb[k * HID + c];
    float bias = srcRole ? 0.f : g_b1eff[l][c];
    float* dst = srcRole ? g_Psrc : g_Pdst;
    int nCh = (srcRole ? NATOM : NNODE) / 4;
    int b0 = srcRole ? (blockIdx.x - PD_BLOCKS) : blockIdx.x;
    int nBlk = srcRole ? PS_BLOCKS : PD_BLOCKS;
    __shared__ __align__(16) float hsh[4 * CODE];
    const float* hsrc = g_h[cur];
    for (int ch = b0; ch < nCh; ch += nBlk) {
        int n0 = ch * 4;
        hsh[c]       = hsrc[n0 * CODE + c];
        hsh[c + 128] = hsrc[n0 * CODE + 128 + c];
        __syncthreads();
#pragma unroll
        for (int q = 0; q < 4; q++) {
            float acc = bias;
            const float4* h4 = (const float4*)(hsh + q * CODE);
#pragma unroll
            for (int k4 = 0; k4 < 16; k4++) {
                float4 hv = h4[k4];
                acc = fmaf(hv.x, w[4*k4+0], acc);
                acc = fmaf(hv.y, w[4*k4+1], acc);
                acc = fmaf(hv.z, w[4*k4+2], acc);
                acc = fmaf(hv.w, w[4*k4+3], acc);
            }
            dst[(n0 + q) * HID + c] = acc;
        }
        __syncthreads();
    }
}

// ================= k_edge: R4 structure + chunked node locality + early prefetch =================
__global__ void __launch_bounds__(128, 5) k_edge(
    const float* __restrict__ b2, const float* __restrict__ lng,
    const float* __restrict__ lnb, int l, int cur, int last,
    float* __restrict__ out)
{
    __shared__ __align__(16) float4 sG[2][KG][5];   // 5KB
    __shared__ int    sNbr[2][KG];
    __shared__ __align__(16) float sHS[2][HID];
    __shared__ float2 sred[2][2];

    int t = threadIdx.x;
    int half = t >> 6, c = t & 63, lane = t & 31, hw = (t >> 5) & 1;
    int barid = 1 + half;

    // contiguous pair range for this block (locality!)
    int p0, p1;
    if (blockIdx.x < ABLK) {
        if (last) return;                          // atom outputs unused in last layer
        p0 = blockIdx.x * ACHUNK;
        p1 = min(p0 + ACHUNK, APAIRS);
    } else {
        p0 = APAIRS + (blockIdx.x - ABLK) * GCHUNK;
        p1 = min(p0 + GCHUNK, APAIRS + GPAIRS);
    }
    if (p0 >= p1) return;

    u64 ewp0[10], ewp1[10];
    const float* ew = g_EW1[l];
#pragma unroll
    for (int i = 0; i < 10; i++) {
        ewp0[i] = pk(ew[(2*i)*HID + 2*c],     ew[(2*i+1)*HID + 2*c]);
        ewp1[i] = pk(ew[(2*i)*HID + 2*c + 1], ew[(2*i+1)*HID + 2*c + 1]);
    }
    u64 Cp = ((const u64*)g_C[l])[c];
    float b2c = b2[c], gmc = lng[c], bbc = lnb[c];

    const u64* psrcq = (const u64*)g_Psrc;
    const u64* pdstq = (const u64*)g_Pdst;
    const float* hcur = g_h[cur];
    const ulonglong2* w2q = (const ulonglong2*)g_W2q[l];

    for (int p = p0; p < p1; p++) {
        int n = 2 * p + half;
        bool atom = n < NATOM;
        int k = atom ? KA : KG;

        // early prefetch (independent of smem staging)
        u64 pd = pdstq[n * 64 + c];
        float hres = __ldg(&hcur[n * CODE + c]);

        if (c < k) {
            int jr = atom ? g_nbrA[n][c] : g_nbrG[n - NATOM][c];
            sNbr[half][c] = jr;
            if (!(jr & CLIPBIT)) {
                const float4* src = atom ? &g_gsA[(n * KA + c) * 5]
                                         : &g_gsG[((n - NATOM) * KG + c) * 5];
#pragma unroll
                for (int i = 0; i < 5; i++) sG[half][c][i] = src[i];
            }
        }
        barhalf(barid);                       // (A) staging ready

        float hs0 = 0.f, hs1 = 0.f;
        const int* nb_ = sNbr[half];
        for (int j0 = 0; j0 < k; j0 += 8) {
            int nf[8]; u64 ps[8];
#pragma unroll
            for (int m = 0; m < 8; m++) {
                nf[m] = nb_[j0 + m];
                ps[m] = psrcq[(nf[m] & NMASK) * 64 + c];
            }
#pragma unroll
            for (int m = 0; m < 8; m++) {
                u64 bu = add2(pd, ps[m]);
                if (nf[m] & CLIPBIT) {
                    float2 b = upk(add2(bu, Cp));
                    hs0 += fmaxf(b.x, 0.f);
                    hs1 += fmaxf(b.y, 0.f);
                } else {
                    const ulonglong2* gj = (const ulonglong2*)sG[half][j0 + m];
                    u64 A0 = 0ull, A1 = 0ull, B0 = 0ull, B1 = 0ull;
#pragma unroll
                    for (int i2 = 0; i2 < 5; i2++) {
                        ulonglong2 gp = gj[i2];
                        ffma2(A0, gp.x, ewp0[2*i2]);
                        ffma2(B0, gp.x, ewp1[2*i2]);
                        ffma2(A1, gp.y, ewp0[2*i2+1]);
                        ffma2(B1, gp.y, ewp1[2*i2+1]);
                    }
                    float2 b = upk(bu);
                    float2 va = upk(add2(A0, A1)), vb = upk(add2(B0, B1));
                    hs0 += fmaxf(b.x + va.x + va.y, 0.f);
                    hs1 += fmaxf(b.y + vb.x + vb.y, 0.f);
                }
            }
        }
        ((float2*)sHS[half])[c] = make_float2(hs0, hs1);
        barhalf(barid);                       // (B) sHS ready

        // ---- stage 2: aggr = mean(hidden) @ W2 (L1-resident __ldg) ----
        u64 acc0 = 0ull, acc1 = 0ull;
        const ulonglong2* hq = (const ulonglong2*)sHS[half];
#pragma unroll 8
        for (int k4 = 0; k4 < 32; k4++) {
            ulonglong2 hv = hq[k4];
            ulonglong2 wv = __ldg(&w2q[k4 * CODE + c]);
            ffma2(acc0, hv.x, wv.x);
            ffma2(acc1, hv.y, wv.y);
        }
        float2 a0 = upk(acc0), a1 = upk(acc1);
        float x = hres + (a0.x + a0.y + a1.x + a1.y) * (atom ? (1.f/KA) : (1.f/KG)) + b2c;

        // ---- single-pass LN ----
        float s1 = x, s2 = x * x;
#pragma unroll
        for (int off = 16; off; off >>= 1) {
            s1 += __shfl_xor_sync(0xffffffffu, s1, off);
            s2 += __shfl_xor_sync(0xffffffffu, s2, off);
        }
        if (lane == 0) sred[half][hw] = make_float2(s1, s2);
        barhalf(barid);                       // (C) sred ready
        float2 ra = sred[half][0], rb = sred[half][1];
        float mu  = (ra.x + rb.x) * (1.f / CODE);
        float var = (ra.y + rb.y) * (1.f / CODE) - mu * mu;
        float y = (x - mu) * rsqrtf(var + 1e-5f) * gmc + bbc;
        if (last) out[(n - NATOM) * CODE + c] = y;
        else      g_h[cur ^ 1][n * CODE + c] = y;
    }
}

// ---------------- launch ----------------
extern "C" void kernel_launch(void* const* d_in, const int* in_sizes, int n_in,
                              void* d_out, int out_size) {
    const float* pos    = (const float*)d_in[0];
    const int*   atype  = (const int*)  d_in[1];
    const float* edge_W = (const float*)d_in[3];
    const float* edge_b = (const float*)d_in[4];
    const float* W1     = (const float*)d_in[5];
    const float* b1     = (const float*)d_in[6];
    const float* W2     = (const float*)d_in[7];
    const float* b2     = (const float*)d_in[8];
    const float* lng    = (const float*)d_in[9];
    const float* lnb    = (const float*)d_in[10];
    float* out = (float*)d_out;

    GaussC gc;
    {
        double off[NGAUSS], dd[NGAUSS];
        double hi = log(6.0);
        for (int g = 0; g < NGAUSS; g++) off[g] = exp(hi * (double)g / 19.0) - 1.0;
        for (int g = NGAUSS - 1; g >= 1; g--) dd[g] = off[g] - off[g-1];
        dd[0] = dd[1];
        for (int g = 0; g < NGAUSS; g++) {
            double coeff = -0.5 / (dd[g] * dd[g]);
            gc.off[g]    = (float)off[g];
            gc.coeff2[g] = (float)(coeff * 1.4426950408889634);
            double d5 = 5.0 - off[g];
            gc.g5[g]   = (float)exp(coeff * d5 * d5);
        }
    }

    k_setup<<<2232 + NL*NGAUSS + 3*NL, 128>>>(pos, atype, edge_W, edge_b, W1, b1, W2, gc);
    k_gauss<<<(NEDGE + 255) / 256, 256>>>(gc);

    int cur = 0;
    for (int l = 0; l < NL; l++) {
        int last = (l == NL - 1) ? 1 : 0;
        k_proj<<<PD_BLOCKS + PS_BLOCKS, 128>>>(W1 + l*MIROWS*HID, l, cur);
        k_edge<<<EDGE_BLOCKS, 128>>>(b2 + l*CODE, lng + l*CODE, lnb + l*CODE,
                                     l, cur, last, out);
        cur ^= 1;
    }
}